// round 6
// baseline (speedup 1.0000x reference)
#include <cuda_runtime.h>
#include <stdint.h>

// LSTM, B=4096, T=2048, I=1, H=10.
// Round 6: FULL-CHIP SPREAD. 148 blocks x 5 warps (160 thr) instead of
// 86 x 8: per SM the SMSP load drops from 2 warps everywhere to (2,1,1,1),
// and surplus warps (ids >= 683) whole-warp exit so 57 SMs run 1 warp/SMSP.
// Math identical to round 4/5: smem h-broadcast (STS.64 + syncwarp + LDS.128,
// parity double-buffered), tanh-only activations, h'=2h folding, f32x2 packing.
// Stagger applied to warp 4 (it shares SMSP0 with warp 0).

#define FULL_MASK 0xFFFFFFFFu

constexpr int Bv = 4096;
constexpr int Tv = 2048;
constexpr int Hv = 10;
constexpr int NGROUPS = Bv / 2;            // 2048 batch-pairs
constexpr int WARPS_PER_BLOCK = 5;         // SMSPs: (2,1,1,1) before exits
constexpr int GROUPS_PER_WARP = 3;
constexpr int NBLOCKS = 148;               // one per SM
constexpr int THREADS = WARPS_PER_BLOCK * 32;  // 160

__device__ __forceinline__ unsigned long long pack2(float lo, float hi) {
    unsigned long long r;
    asm("mov.b64 %0, {%1, %2};" : "=l"(r) : "f"(lo), "f"(hi));
    return r;
}
__device__ __forceinline__ void unpack2(unsigned long long v, float& lo, float& hi) {
    asm("mov.b64 {%0, %1}, %2;" : "=f"(lo), "=f"(hi) : "l"(v));
}
__device__ __forceinline__ unsigned long long fma2(unsigned long long a,
                                                   unsigned long long b,
                                                   unsigned long long c) {
    unsigned long long d;
    asm("fma.rn.f32x2 %0, %1, %2, %3;" : "=l"(d) : "l"(a), "l"(b), "l"(c));
    return d;
}
__device__ __forceinline__ unsigned long long mul2(unsigned long long a,
                                                   unsigned long long b) {
    unsigned long long d;
    asm("mul.rn.f32x2 %0, %1, %2;" : "=l"(d) : "l"(a), "l"(b));
    return d;
}
__device__ __forceinline__ float tanh_a(float x) {
    float r; asm("tanh.approx.f32 %0, %1;" : "=f"(r) : "f"(x)); return r;
}

__global__ void __launch_bounds__(THREADS, 1)
lstm_kernel(const float* __restrict__ x,
            const float* __restrict__ W_ih,   // [40,1]
            const float* __restrict__ W_hh,   // [40,10]
            const float* __restrict__ b_ih,   // [40]
            const float* __restrict__ b_hh,   // [40]
            const float* __restrict__ W_out,  // [1,10]
            const float* __restrict__ b_out,  // [1]
            float* __restrict__ out)          // [4096]
{
    // Double-buffered h exchange: [parity][warp][group][unit], 12-ull stride
    // (96B) keeps LDS.128 16B-aligned.
    __shared__ __align__(16) unsigned long long hbuf[2][WARPS_PER_BLOCK][4][12];

    const int warp = threadIdx.x >> 5;
    const int lane = threadIdx.x & 31;
    const int gw   = blockIdx.x * WARPS_PER_BLOCK + warp;   // global warp id
    // Whole-warp early exit: frees the SMSP (no block barriers used).
    if (gw * GROUPS_PER_WARP >= NGROUPS) return;

    const int g    = lane / 10;               // 0..2 real groups, 3 = idle lanes
    const int j    = lane - g * 10;           // hidden unit owned by this lane
    const int base = g * 10;
    const int slot = gw * GROUPS_PER_WARP + g;
    const bool active = (g < 3) && (slot < NGROUPS);
    const int s  = active ? slot : 0;
    const int bA = 2 * s;
    const int bB = 2 * s + 1;

    // ---- Per-lane weights (rows q*10+j, gate order i,f,g,o).
    // Sigmoid gates (q=0,1,3): pre-scaled by 0.5. h is h'=2h -> W_hh *0.5 more.
    unsigned long long w2[4][10], bias2[4], wih2[4];
#pragma unroll
    for (int q = 0; q < 4; q++) {
        const float gs = (q == 2) ? 1.0f : 0.5f;
        const int row = q * 10 + j;
        const float bb = (b_ih[row] + b_hh[row]) * gs;
        bias2[q] = pack2(bb, bb);
        const float wi = W_ih[row] * gs;           // I == 1
        wih2[q] = pack2(wi, wi);
        const float hs = gs * 0.5f;
#pragma unroll
        for (int k = 0; k < 10; k++) {
            const float w = W_hh[row * Hv + k] * hs;
            w2[q][k] = pack2(w, w);
        }
    }
    const unsigned long long half2 = pack2(0.5f, 0.5f);

    // ---- State
    unsigned long long h2[10];
#pragma unroll
    for (int k = 0; k < 10; k++) h2[k] = 0ull;
    unsigned long long c2 = 0ull;
    float hA = 0.f, hB = 0.f;                      // own unit h' (for epilogue)

    unsigned long long* myst0 = &hbuf[0][warp][g][j];
    unsigned long long* myst1 = &hbuf[1][warp][g][j];
    const ulonglong2* grp0 = reinterpret_cast<const ulonglong2*>(&hbuf[0][warp][g][0]);
    const ulonglong2* grp1 = reinterpret_cast<const ulonglong2*>(&hbuf[1][warp][g][0]);

    const float4* xA4 = reinterpret_cast<const float4*>(x + (size_t)bA * Tv);
    const float4* xB4 = reinterpret_cast<const float4*>(x + (size_t)bB * Tv);
    float4 nA = xA4[0], nB = xB4[0];               // double-buffered x

    // ---- Anti-phase stagger for the one SMSP that carries 2 warps
    // (warps 0 and 4 both map to SMSP0). Delay warp 4 by ~150 cycles.
    if (warp == 4) {
        float d = 1.0f + (float)lane;
#pragma unroll
        for (int it = 0; it < 37; it++) d = fmaf(d, 1.0000001f, 1.0f);
        if (d == -1.0f) out[0] = d;                // never true; keeps the chain
    }

    for (int t0 = 0; t0 < Tv; t0 += 4) {
        const float4 curA = nA, curB = nB;
        const int nxt = (t0 >> 2) + 1;
        if (nxt < Tv / 4) { nA = xA4[nxt]; nB = xB4[nxt]; }

#pragma unroll
        for (int u = 0; u < 4; u++) {
            const float xa = (u == 0) ? curA.x : (u == 1) ? curA.y : (u == 2) ? curA.z : curA.w;
            const float xb = (u == 0) ? curB.x : (u == 1) ? curB.y : (u == 2) ? curB.z : curB.w;
            const unsigned long long x2 = pack2(xa, xb);

            // 4 independent 11-deep chains; g and i first (deepest epilogue path).
            unsigned long long ag = fma2(x2, wih2[2], bias2[2]);
            unsigned long long ai = fma2(x2, wih2[0], bias2[0]);
            unsigned long long af = fma2(x2, wih2[1], bias2[1]);
            unsigned long long ao = fma2(x2, wih2[3], bias2[3]);
#pragma unroll
            for (int k = 0; k < 10; k++) {
                ag = fma2(h2[k], w2[2][k], ag);
                ai = fma2(h2[k], w2[0][k], ai);
                af = fma2(h2[k], w2[1][k], af);
                ao = fma2(h2[k], w2[3][k], ao);
            }

            float agA, agB, aiA, aiB, afA, afB, aoA, aoB;
            unpack2(ag, agA, agB);
            unpack2(ai, aiA, aiB);
            unpack2(af, afA, afB);
            unpack2(ao, aoA, aoB);

            const float tgA = tanh_a(agA), tgB = tanh_a(agB);
            const float tiA = tanh_a(aiA), tiB = tanh_a(aiB);
            const float tfA = tanh_a(afA), tfB = tanh_a(afB);
            const float toA = tanh_a(aoA), toB = tanh_a(aoB);

            // i = 0.5*ti+0.5, f = 0.5*tf+0.5, c = f*c + i*g, h' = to*tc + tc.
            const unsigned long long ti2 = pack2(tiA, tiB);
            const unsigned long long tf2 = pack2(tfA, tfB);
            const unsigned long long tg2 = pack2(tgA, tgB);
            const unsigned long long i2  = fma2(half2, ti2, half2);
            const unsigned long long f2  = fma2(half2, tf2, half2);
            const unsigned long long ig2 = mul2(i2, tg2);
            c2 = fma2(f2, c2, ig2);

            float cA, cB;
            unpack2(c2, cA, cB);
            const float tcA = tanh_a(cA);
            const float tcB = tanh_a(cB);
            hA = fmaf(toA, tcA, tcA);
            hB = fmaf(toB, tcB, tcB);

            // Broadcast h' through shared memory (parity double-buffered).
            const unsigned long long hself = pack2(hA, hB);
            if ((u & 1) == 0) {
                *myst0 = hself;
                __syncwarp();
#pragma unroll
                for (int m = 0; m < 5; m++) {
                    const ulonglong2 v = grp0[m];
                    h2[2 * m] = v.x;
                    h2[2 * m + 1] = v.y;
                }
            } else {
                *myst1 = hself;
                __syncwarp();
#pragma unroll
                for (int m = 0; m < 5; m++) {
                    const ulonglong2 v = grp1[m];
                    h2[2 * m] = v.x;
                    h2[2 * m + 1] = v.y;
                }
            }
        }
    }

    // ---- Epilogue: out[b] = h . W_out + b_out, with h = 0.5*h'.
    const float wo = W_out[j] * 0.5f;
    const float pA = hA * wo;
    const float pB = hB * wo;
    float sA = 0.f, sB = 0.f;
#pragma unroll
    for (int k = 0; k < 10; k++) {
        sA += __shfl_sync(FULL_MASK, pA, base + k);
        sB += __shfl_sync(FULL_MASK, pB, base + k);
    }
    if (active && j == 0) {
        const float bo = b_out[0];
        out[bA] = sA + bo;
        out[bB] = sB + bo;
    }
}

extern "C" void kernel_launch(void* const* d_in, const int* in_sizes, int n_in,
                              void* d_out, int out_size) {
    (void)in_sizes; (void)n_in; (void)out_size;
    const float* x     = (const float*)d_in[0];
    const float* W_ih  = (const float*)d_in[1];
    const float* W_hh  = (const float*)d_in[2];
    const float* b_ih  = (const float*)d_in[3];
    const float* b_hh  = (const float*)d_in[4];
    const float* W_out = (const float*)d_in[5];
    const float* b_out = (const float*)d_in[6];
    float* out = (float*)d_out;

    lstm_kernel<<<NBLOCKS, THREADS>>>(x, W_ih, W_hh, b_ih, b_hh, W_out, b_out, out);
}

// round 7
// speedup vs baseline: 1.0158x; 1.0158x over previous
#include <cuda_runtime.h>
#include <stdint.h>

// LSTM, B=4096, T=2048, I=1, H=10.
// Round 7: latency-targeted. (a) Each gate's 11-deep FFMA2 chain split into
// two ~5-deep halves + add2 (depth ~44 -> ~28 cyc). (b) tanh issue order puts
// the c-critical gates (g,i,f) first, o last. Everything else as round 6:
// 148x5 launch, smem h-broadcast, tanh-only activations, h'=2h folding.

#define FULL_MASK 0xFFFFFFFFu

constexpr int Bv = 4096;
constexpr int Tv = 2048;
constexpr int Hv = 10;
constexpr int NGROUPS = Bv / 2;            // 2048 batch-pairs
constexpr int WARPS_PER_BLOCK = 5;
constexpr int GROUPS_PER_WARP = 3;
constexpr int NBLOCKS = 148;
constexpr int THREADS = WARPS_PER_BLOCK * 32;  // 160

__device__ __forceinline__ unsigned long long pack2(float lo, float hi) {
    unsigned long long r;
    asm("mov.b64 %0, {%1, %2};" : "=l"(r) : "f"(lo), "f"(hi));
    return r;
}
__device__ __forceinline__ void unpack2(unsigned long long v, float& lo, float& hi) {
    asm("mov.b64 {%0, %1}, %2;" : "=f"(lo), "=f"(hi) : "l"(v));
}
__device__ __forceinline__ unsigned long long fma2(unsigned long long a,
                                                   unsigned long long b,
                                                   unsigned long long c) {
    unsigned long long d;
    asm("fma.rn.f32x2 %0, %1, %2, %3;" : "=l"(d) : "l"(a), "l"(b), "l"(c));
    return d;
}
__device__ __forceinline__ unsigned long long mul2(unsigned long long a,
                                                   unsigned long long b) {
    unsigned long long d;
    asm("mul.rn.f32x2 %0, %1, %2;" : "=l"(d) : "l"(a), "l"(b));
    return d;
}
__device__ __forceinline__ unsigned long long add2(unsigned long long a,
                                                   unsigned long long b) {
    unsigned long long d;
    asm("add.rn.f32x2 %0, %1, %2;" : "=l"(d) : "l"(a), "l"(b));
    return d;
}
__device__ __forceinline__ float tanh_a(float x) {
    float r; asm("tanh.approx.f32 %0, %1;" : "=f"(r) : "f"(x)); return r;
}

__global__ void __launch_bounds__(THREADS, 1)
lstm_kernel(const float* __restrict__ x,
            const float* __restrict__ W_ih,   // [40,1]
            const float* __restrict__ W_hh,   // [40,10]
            const float* __restrict__ b_ih,   // [40]
            const float* __restrict__ b_hh,   // [40]
            const float* __restrict__ W_out,  // [1,10]
            const float* __restrict__ b_out,  // [1]
            float* __restrict__ out)          // [4096]
{
    __shared__ __align__(16) unsigned long long hbuf[2][WARPS_PER_BLOCK][4][12];

    const int warp = threadIdx.x >> 5;
    const int lane = threadIdx.x & 31;
    const int gw   = blockIdx.x * WARPS_PER_BLOCK + warp;
    if (gw * GROUPS_PER_WARP >= NGROUPS) return;   // whole-warp exit

    const int g    = lane / 10;
    const int j    = lane - g * 10;
    const int base = g * 10;
    const int slot = gw * GROUPS_PER_WARP + g;
    const bool active = (g < 3) && (slot < NGROUPS);
    const int s  = active ? slot : 0;
    const int bA = 2 * s;
    const int bB = 2 * s + 1;

    // Weights: gate order i,f,g,o; sigmoid gates (0,1,3) pre-scaled 0.5;
    // h stored as h'=2h -> extra 0.5 on W_hh.
    unsigned long long w2[4][10], bias2[4], wih2[4];
#pragma unroll
    for (int q = 0; q < 4; q++) {
        const float gs = (q == 2) ? 1.0f : 0.5f;
        const int row = q * 10 + j;
        const float bb = (b_ih[row] + b_hh[row]) * gs;
        bias2[q] = pack2(bb, bb);
        const float wi = W_ih[row] * gs;
        wih2[q] = pack2(wi, wi);
        const float hs = gs * 0.5f;
#pragma unroll
        for (int k = 0; k < 10; k++) {
            const float w = W_hh[row * Hv + k] * hs;
            w2[q][k] = pack2(w, w);
        }
    }
    const unsigned long long half2 = pack2(0.5f, 0.5f);

    unsigned long long h2[10];
#pragma unroll
    for (int k = 0; k < 10; k++) h2[k] = 0ull;
    unsigned long long c2 = 0ull;
    float hA = 0.f, hB = 0.f;

    unsigned long long* myst0 = &hbuf[0][warp][g][j];
    unsigned long long* myst1 = &hbuf[1][warp][g][j];
    const ulonglong2* grp0 = reinterpret_cast<const ulonglong2*>(&hbuf[0][warp][g][0]);
    const ulonglong2* grp1 = reinterpret_cast<const ulonglong2*>(&hbuf[1][warp][g][0]);

    const float4* xA4 = reinterpret_cast<const float4*>(x + (size_t)bA * Tv);
    const float4* xB4 = reinterpret_cast<const float4*>(x + (size_t)bB * Tv);
    float4 nA = xA4[0], nB = xB4[0];

    // Anti-phase stagger for the doubled SMSP0 (warps 0 and 4).
    if (warp == 4) {
        float d = 1.0f + (float)lane;
#pragma unroll
        for (int it = 0; it < 37; it++) d = fmaf(d, 1.0000001f, 1.0f);
        if (d == -1.0f) out[0] = d;                // never true
    }

    for (int t0 = 0; t0 < Tv; t0 += 4) {
        const float4 curA = nA, curB = nB;
        const int nxt = (t0 >> 2) + 1;
        if (nxt < Tv / 4) { nA = xA4[nxt]; nB = xB4[nxt]; }

#pragma unroll
        for (int u = 0; u < 4; u++) {
            const float xa = (u == 0) ? curA.x : (u == 1) ? curA.y : (u == 2) ? curA.z : curA.w;
            const float xb = (u == 0) ? curB.x : (u == 1) ? curB.y : (u == 2) ? curB.z : curB.w;
            const unsigned long long x2 = pack2(xa, xb);

            // Split matvec: per gate two ~5-deep halves (front half seeded by
            // the h-independent x*wih+bias, back half by a mul), then one add.
            // Gate order in arrays: 0=i,1=f,2=g,3=o; compute g,i,f trees with
            // priority (they gate the c path).
            unsigned long long fA_[4], fB_[4];
#pragma unroll
            for (int q = 0; q < 4; q++) {
                fA_[q] = fma2(x2, wih2[q], bias2[q]);     // h-independent seed
                fB_[q] = mul2(h2[5], w2[q][5]);
            }
#pragma unroll
            for (int k = 0; k < 5; k++) {
                fA_[2] = fma2(h2[k], w2[2][k], fA_[2]);
                fA_[0] = fma2(h2[k], w2[0][k], fA_[0]);
                fA_[1] = fma2(h2[k], w2[1][k], fA_[1]);
                fA_[3] = fma2(h2[k], w2[3][k], fA_[3]);
                if (k < 4) {
                    fB_[2] = fma2(h2[6 + k], w2[2][6 + k], fB_[2]);
                    fB_[0] = fma2(h2[6 + k], w2[0][6 + k], fB_[0]);
                    fB_[1] = fma2(h2[6 + k], w2[1][6 + k], fB_[1]);
                    fB_[3] = fma2(h2[6 + k], w2[3][6 + k], fB_[3]);
                }
            }
            const unsigned long long ag = add2(fA_[2], fB_[2]);
            const unsigned long long ai = add2(fA_[0], fB_[0]);
            const unsigned long long af = add2(fA_[1], fB_[1]);
            const unsigned long long ao = add2(fA_[3], fB_[3]);

            float agA, agB, aiA, aiB, afA, afB, aoA, aoB;
            unpack2(ag, agA, agB);
            unpack2(ai, aiA, aiB);
            unpack2(af, afA, afB);
            unpack2(ao, aoA, aoB);

            // MUFU order: c-critical first (g,i,f), o last.
            const float tgA = tanh_a(agA), tgB = tanh_a(agB);
            const float tiA = tanh_a(aiA), tiB = tanh_a(aiB);
            const float tfA = tanh_a(afA), tfB = tanh_a(afB);

            const unsigned long long ti2 = pack2(tiA, tiB);
            const unsigned long long tf2 = pack2(tfA, tfB);
            const unsigned long long tg2 = pack2(tgA, tgB);
            const unsigned long long i2  = fma2(half2, ti2, half2);
            const unsigned long long f2  = fma2(half2, tf2, half2);
            const unsigned long long ig2 = mul2(i2, tg2);
            c2 = fma2(f2, c2, ig2);

            const float toA = tanh_a(aoA), toB = tanh_a(aoB);

            float cA, cB;
            unpack2(c2, cA, cB);
            const float tcA = tanh_a(cA);
            const float tcB = tanh_a(cB);
            hA = fmaf(toA, tcA, tcA);                  // h' = 2h
            hB = fmaf(toB, tcB, tcB);

            const unsigned long long hself = pack2(hA, hB);
            if ((u & 1) == 0) {
                *myst0 = hself;
                __syncwarp();
#pragma unroll
                for (int m = 0; m < 5; m++) {
                    const ulonglong2 v = grp0[m];
                    h2[2 * m] = v.x;
                    h2[2 * m + 1] = v.y;
                }
            } else {
                *myst1 = hself;
                __syncwarp();
#pragma unroll
                for (int m = 0; m < 5; m++) {
                    const ulonglong2 v = grp1[m];
                    h2[2 * m] = v.x;
                    h2[2 * m + 1] = v.y;
                }
            }
        }
    }

    // Epilogue: out[b] = h . W_out + b_out, h = 0.5*h'.
    const float wo = W_out[j] * 0.5f;
    const float pA = hA * wo;
    const float pB = hB * wo;
    float sA = 0.f, sB = 0.f;
#pragma unroll
    for (int k = 0; k < 10; k++) {
        sA += __shfl_sync(FULL_MASK, pA, base + k);
        sB += __shfl_sync(FULL_MASK, pB, base + k);
    }
    if (active && j == 0) {
        const float bo = b_out[0];
        out[bA] = sA + bo;
        out[bB] = sB + bo;
    }
}

extern "C" void kernel_launch(void* const* d_in, const int* in_sizes, int n_in,
                              void* d_out, int out_size) {
    (void)in_sizes; (void)n_in; (void)out_size;
    const float* x     = (const float*)d_in[0];
    const float* W_ih  = (const float*)d_in[1];
    const float* W_hh  = (const float*)d_in[2];
    const float* b_ih  = (const float*)d_in[3];
    const float* b_hh  = (const float*)d_in[4];
    const float* W_out = (const float*)d_in[5];
    const float* b_out = (const float*)d_in[6];
    float* out = (float*)d_out;

    lstm_kernel<<<NBLOCKS, THREADS>>>(x, W_ih, W_hh, b_ih, b_hh, W_out, b_out, out);
}

// round 8
// speedup vs baseline: 1.2918x; 1.2717x over previous
#include <cuda_runtime.h>
#include <stdint.h>

// LSTM, B=4096, T=2048, I=1, H=10.
// Round 8: UNPACKED scalar design. Lane = (batch, unit): each warp carries
// 3 single batches (30 lanes), 1366 warps total. Halves the per-warp serial
// step (49 FFMA + 5 MUFU + small exchange ~= 230 cyc vs 394) at the cost of
// 2.3 warps/SMSP contention. Same math: tanh-only activations with
// sigmoid = 0.5*tanh(a/2)+0.5 folded into weights, h stored as h'=2h.

#define FULL_MASK 0xFFFFFFFFu

constexpr int Bv = 4096;
constexpr int Tv = 2048;
constexpr int Hv = 10;
constexpr int BATCH_PER_WARP = 3;
constexpr int WARPS_PER_BLOCK = 10;
constexpr int NBLOCKS = 148;                   // 1480 warps launched, 1366 live
constexpr int THREADS = WARPS_PER_BLOCK * 32;  // 320

__device__ __forceinline__ float tanh_a(float x) {
    float r; asm("tanh.approx.f32 %0, %1;" : "=f"(r) : "f"(x)); return r;
}

__global__ void __launch_bounds__(THREADS, 1)
lstm_kernel(const float* __restrict__ x,
            const float* __restrict__ W_ih,   // [40,1]
            const float* __restrict__ W_hh,   // [40,10]
            const float* __restrict__ b_ih,   // [40]
            const float* __restrict__ b_hh,   // [40]
            const float* __restrict__ W_out,  // [1,10]
            const float* __restrict__ b_out,  // [1]
            float* __restrict__ out)          // [4096]
{
    // h exchange: [parity][warp][group][unit], 12-float stride (48B) keeps
    // the float4 reads 16B-aligned. 2*10*4*12*4B = 3840B.
    __shared__ __align__(16) float hbuf[2][WARPS_PER_BLOCK][4][12];

    const int warp = threadIdx.x >> 5;
    const int lane = threadIdx.x & 31;
    const int gw   = blockIdx.x * WARPS_PER_BLOCK + warp;
    if (gw * BATCH_PER_WARP >= Bv) return;     // whole-warp exit

    const int g    = lane / 10;                // 0..2 batches, 3 = idle lanes
    const int j    = lane - g * 10;            // hidden unit owned by this lane
    const int base = g * 10;
    const int batch = gw * BATCH_PER_WARP + g;
    const bool active = (g < 3) && (batch < Bv);
    const int b = active ? batch : 0;          // clamp for safe loads

    // ---- Per-lane weights (rows q*10+j, gate order i,f,g,o).
    // Sigmoid gates (q=0,1,3): inputs pre-scaled 0.5 (sigm(a)=0.5*tanh(a/2)+0.5).
    // h stored as h'=2h -> W_hh gets an extra 0.5.
    float w[4][10], wih[4], bias[4];
#pragma unroll
    for (int q = 0; q < 4; q++) {
        const float gs = (q == 2) ? 1.0f : 0.5f;
        const int row = q * 10 + j;
        bias[q] = (b_ih[row] + b_hh[row]) * gs;
        wih[q]  = W_ih[row] * gs;              // I == 1
        const float hs = gs * 0.5f;
#pragma unroll
        for (int k = 0; k < 10; k++) w[q][k] = W_hh[row * Hv + k] * hs;
    }

    // ---- State
    float h2[10];
#pragma unroll
    for (int k = 0; k < 10; k++) h2[k] = 0.f;
    float c = 0.f, hown = 0.f;                 // hown = h' of own unit

    float* st0 = &hbuf[0][warp][g][j];
    float* st1 = &hbuf[1][warp][g][j];
    const float4* grp0 = reinterpret_cast<const float4*>(&hbuf[0][warp][g][0]);
    const float4* grp1 = reinterpret_cast<const float4*>(&hbuf[1][warp][g][0]);

    const float4* x4 = reinterpret_cast<const float4*>(x + (size_t)b * Tv);
    float4 nx = x4[0];                         // double-buffered x (4 steps/load)

    for (int t0 = 0; t0 < Tv; t0 += 4) {
        const float4 cur = nx;
        const int nxt = (t0 >> 2) + 1;
        if (nxt < Tv / 4) nx = x4[nxt];

#pragma unroll
        for (int u = 0; u < 4; u++) {
            const float xt = (u == 0) ? cur.x : (u == 1) ? cur.y : (u == 2) ? cur.z : cur.w;

            // 4 independent 11-deep scalar chains.
            float ag = fmaf(xt, wih[2], bias[2]);
            float ai = fmaf(xt, wih[0], bias[0]);
            float af = fmaf(xt, wih[1], bias[1]);
            float ao = fmaf(xt, wih[3], bias[3]);
#pragma unroll
            for (int k = 0; k < 10; k++) {
                ag = fmaf(h2[k], w[2][k], ag);
                ai = fmaf(h2[k], w[0][k], ai);
                af = fmaf(h2[k], w[1][k], af);
                ao = fmaf(h2[k], w[3][k], ao);
            }

            // 4 MUFU (inputs already gate-scaled), c-critical first.
            const float tg = tanh_a(ag);
            const float ti = tanh_a(ai);
            const float tf = tanh_a(af);
            const float to = tanh_a(ao);

            const float iv = fmaf(0.5f, ti, 0.5f);
            const float fv = fmaf(0.5f, tf, 0.5f);
            c = fmaf(fv, c, iv * tg);
            const float tc = tanh_a(c);
            hown = fmaf(to, tc, tc);           // h' = 2h

            // Broadcast h' through shared memory (parity double-buffered).
            if ((u & 1) == 0) {
                *st0 = hown;
                __syncwarp();
                const float4 v0 = grp0[0];
                const float4 v1 = grp0[1];
                const float2 v2 = reinterpret_cast<const float2*>(grp0)[4];
                h2[0] = v0.x; h2[1] = v0.y; h2[2] = v0.z; h2[3] = v0.w;
                h2[4] = v1.x; h2[5] = v1.y; h2[6] = v1.z; h2[7] = v1.w;
                h2[8] = v2.x; h2[9] = v2.y;
            } else {
                *st1 = hown;
                __syncwarp();
                const float4 v0 = grp1[0];
                const float4 v1 = grp1[1];
                const float2 v2 = reinterpret_cast<const float2*>(grp1)[4];
                h2[0] = v0.x; h2[1] = v0.y; h2[2] = v0.z; h2[3] = v0.w;
                h2[4] = v1.x; h2[5] = v1.y; h2[6] = v1.z; h2[7] = v1.w;
                h2[8] = v2.x; h2[9] = v2.y;
            }
        }
    }

    // ---- Epilogue: out[b] = h . W_out + b_out, with h = 0.5*h'.
    const float p = hown * (W_out[j] * 0.5f);
    float sum = 0.f;
#pragma unroll
    for (int k = 0; k < 10; k++) {
        sum += __shfl_sync(FULL_MASK, p, base + k);
    }
    if (active && j == 0) {
        out[b] = sum + b_out[0];
    }
}

extern "C" void kernel_launch(void* const* d_in, const int* in_sizes, int n_in,
                              void* d_out, int out_size) {
    (void)in_sizes; (void)n_in; (void)out_size;
    const float* x     = (const float*)d_in[0];
    const float* W_ih  = (const float*)d_in[1];
    const float* W_hh  = (const float*)d_in[2];
    const float* b_ih  = (const float*)d_in[3];
    const float* b_hh  = (const float*)d_in[4];
    const float* W_out = (const float*)d_in[5];
    const float* b_out = (const float*)d_in[6];
    float* out = (float*)d_out;

    lstm_kernel<<<NBLOCKS, THREADS>>>(x, W_ih, W_hh, b_ih, b_hh, W_out, b_out, out);
}